// round 5
// baseline (speedup 1.0000x reference)
#include <cuda_runtime.h>
#include <cuda_bf16.h>
#include <math.h>
#include <stdint.h>

#define B_   32
#define NN   511
#define F_   512
#define F3   1536
#define NP   255   // internal nodes (parents)

// ---------------- scratch (static device memory; no allocations) ----------------
__device__ __align__(16) float g_enode [B_*F_];
__device__ __align__(16) float g_eforw [B_*F_];
__device__ __align__(16) float g_scores[B_*NN];
__device__ __align__(16) float g_logits[B_*NN];
__device__ __align__(16) float g_feat2 [B_*NN*F_];
__device__ __align__(16) float g_feiou [(size_t)B_*NN*F3];
__device__ __align__(16) float g_fefp  [B_*NP*F_];
__device__ __align__(16) float g_h     [B_*NN*F_];
__device__ __align__(16) float g_c     [B_*NN*F_];
__device__ __align__(16) float g_iou_t [B_*128*F3];
__device__ __align__(16) float g_f_t   [B_*256*F_];
// split weights: [N, 1536] bf16, layout [hi | hi | lo] along K'
__device__ __align__(16) __nv_bfloat16 g_wfeiou_s[(size_t)F3*F3];
__device__ __align__(16) __nv_bfloat16 g_wuiou_s [(size_t)F3*F3];
__device__ __align__(16) __nv_bfloat16 g_wfef_s  [(size_t)F_*F3];
__device__ __align__(16) __nv_bfloat16 g_wuf_s   [(size_t)F_*F3];

__device__ __forceinline__ float sigm(float x) { return 1.f / (1.f + expf(-x)); }

__device__ __forceinline__ uint32_t smem_u32(const void* p) {
    uint32_t a;
    asm("{ .reg .u64 t; cvta.to.shared.u64 t, %1; cvt.u32.u64 %0, t; }" : "=r"(a) : "l"(p));
    return a;
}
#define SWZ(o) ((o) ^ (((o) >> 3) & 0x70))

__device__ __forceinline__ uint32_t pack_hi(float a, float b) {
    __nv_bfloat162 h = __float22bfloat162_rn(make_float2(a, b));
    return *reinterpret_cast<uint32_t*>(&h);
}
__device__ __forceinline__ uint32_t pack_lo(float a, float b) {
    float ah = __bfloat162float(__float2bfloat16_rn(a));
    float bh = __bfloat162float(__float2bfloat16_rn(b));
    return pack_hi(a - ah, b - bh);
}

__device__ __forceinline__ void ldmx4(uint32_t* r, uint32_t addr) {
    asm volatile("ldmatrix.sync.aligned.m8n8.x4.shared.b16 {%0,%1,%2,%3}, [%4];"
                 : "=r"(r[0]), "=r"(r[1]), "=r"(r[2]), "=r"(r[3]) : "r"(addr));
}
__device__ __forceinline__ void ldmx2(uint32_t* r, uint32_t addr) {
    asm volatile("ldmatrix.sync.aligned.m8n8.x2.shared.b16 {%0,%1}, [%2];"
                 : "=r"(r[0]), "=r"(r[1]) : "r"(addr));
}
__device__ __forceinline__ void mma16816(float* d, const uint32_t* a, const uint32_t* b) {
    asm volatile("mma.sync.aligned.m16n8k16.row.col.f32.bf16.bf16.f32 "
                 "{%0,%1,%2,%3}, {%4,%5,%6,%7}, {%8,%9}, {%0,%1,%2,%3};"
                 : "+f"(d[0]), "+f"(d[1]), "+f"(d[2]), "+f"(d[3])
                 : "r"(a[0]), "r"(a[1]), "r"(a[2]), "r"(a[3]), "r"(b[0]), "r"(b[1]));
}

// ================= weight split: W[rows,512] fp32 -> [rows,1536] bf16 [hi|hi|lo] ====
__global__ void wsplit_kernel(const float* __restrict__ W, __nv_bfloat16* __restrict__ O,
                              int rows) {
    int idx = blockIdx.x * blockDim.x + threadIdx.x;
    if (idx >= rows * 512) return;
    int r = idx >> 9, k = idx & 511;
    float v = W[idx];
    __nv_bfloat16 hi = __float2bfloat16_rn(v);
    __nv_bfloat16 lo = __float2bfloat16_rn(v - __bfloat162float(hi));
    O[(size_t)r * F3 + k]        = hi;
    O[(size_t)r * F3 + 512 + k]  = hi;
    O[(size_t)r * F3 + 1024 + k] = lo;
}

// ================= mma.sync dual GEMM =================
// C[M,N] = splitK(gather(A))[M,1536] @ Bw[N,1536]^T (+bias); A fp32, split on the fly.
// mode 0: row m = A + m*512
// mode 1: b=m/cnt, node=nodeStart+m%cnt; row = A + b*bstride + node*512
// mode 2: like 1 but row = A[2node+1] + A[2node+2]
struct GP {
    const float* A; const __nv_bfloat16* Bw; const float* bias; float* C;
    int mode, M, N, nodeStart, cnt, bstride, gx;
};

#define TILE_BYTES 16384                // 128 rows x 64 bf16 (128B/row)
#define TC_SMEM (4 * TILE_BYTES + 1024)

__global__ void __launch_bounds__(256) dual_gemm_mma(GP g0, GP g1) {
    extern __shared__ char smem_dyn[];
    const GP& g = (blockIdx.z == 0) ? g0 : g1;
    const int tileN = blockIdx.x * 128;
    const int tileM = blockIdx.y * 128;
    if ((int)blockIdx.x >= g.gx || tileM >= g.M) return;

    const uint32_t sb0 = smem_u32(smem_dyn);
    const uint32_t ab  = (sb0 + 1023u) & ~1023u;
    char* tiles = smem_dyn + (ab - sb0);
    // layout: [buf0 A | buf0 B | buf1 A | buf1 B]
    const int tid = threadIdx.x;
    const int wid = tid >> 5, lane = tid & 31;
    const int mw = (wid & 1) * 64;        // warp M offset
    const int nw = (wid >> 1) * 32;       // warp N offset

    // ---- fill source pointers: 2 threads per row, 4 x 16B chunks each ----
    const int row  = tid >> 1;            // 0..127
    const int c16b = (tid & 1) * 4;       // chunk base 0 or 4
    int row_g = tileM + row; if (row_g >= g.M) row_g = g.M - 1;
    const float *src1, *src2 = nullptr;
    if (g.mode == 0) src1 = g.A + (size_t)row_g * 512;
    else {
        int b = row_g / g.cnt, node = g.nodeStart + row_g % g.cnt;
        if (g.mode == 1) src1 = g.A + (size_t)b * g.bstride + (size_t)node * 512;
        else {
            src1 = g.A + (size_t)b * g.bstride + (size_t)(2 * node + 1) * 512;
            src2 = g.A + (size_t)b * g.bstride + (size_t)(2 * node + 2) * 512;
        }
    }
    const __nv_bfloat16* bsrc = g.Bw + (size_t)(tileN + row) * F3;
    const int mode = g.mode;

    float4 pa0[4], pa1[4], qa0[4], qa1[4];
    uint4  pb[4];

    auto load_chunk = [&](int c) {
        const int kb = (c & 7) * 64;
        #pragma unroll
        for (int s = 0; s < 4; s++) {
            int cs = c16b + s;
            pa0[s] = *(const float4*)(src1 + kb + cs * 8);
            pa1[s] = *(const float4*)(src1 + kb + cs * 8 + 4);
            if (mode == 2) {
                qa0[s] = *(const float4*)(src2 + kb + cs * 8);
                qa1[s] = *(const float4*)(src2 + kb + cs * 8 + 4);
            }
            pb[s] = *(const uint4*)(bsrc + c * 64 + cs * 8);
        }
    };
    auto store_chunk = [&](int c, int buf) {
        char* smA = tiles + buf * 2 * TILE_BYTES;
        char* smB = smA + TILE_BYTES;
        const int seg = c >> 3;
        #pragma unroll
        for (int s = 0; s < 4; s++) {
            int cs = c16b + s;
            float4 v0 = pa0[s], v1 = pa1[s];
            if (mode == 2) {
                v0.x += qa0[s].x; v0.y += qa0[s].y; v0.z += qa0[s].z; v0.w += qa0[s].w;
                v1.x += qa1[s].x; v1.y += qa1[s].y; v1.z += qa1[s].z; v1.w += qa1[s].w;
            }
            uint4 o;
            if (seg == 1) {
                o.x = pack_lo(v0.x, v0.y); o.y = pack_lo(v0.z, v0.w);
                o.z = pack_lo(v1.x, v1.y); o.w = pack_lo(v1.z, v1.w);
            } else {
                o.x = pack_hi(v0.x, v0.y); o.y = pack_hi(v0.z, v0.w);
                o.z = pack_hi(v1.x, v1.y); o.w = pack_hi(v1.z, v1.w);
            }
            int off = row * 128 + cs * 16;
            *(uint4*)(smA + SWZ(off)) = o;
            *(uint4*)(smB + SWZ(off)) = pb[s];
        }
    };

    float acc[4][4][4] = {};

    load_chunk(0);
    store_chunk(0, 0);
    __syncthreads();

    const int nt = 24;                    // 1536 / 64
    // precomputed ldmatrix intra-tile offsets
    const int a_r = lane & 15, a_q = (lane >> 4) * 16;
    const int b_r = lane & 7,  b_q = ((lane >> 3) & 1) * 16;

    for (int t = 0; t < nt; t++) {
        const int buf = t & 1;
        if (t + 1 < nt) load_chunk(t + 1);

        const uint32_t sAb = ab + buf * 2 * TILE_BYTES;
        const uint32_t sBb = sAb + TILE_BYTES;
        #pragma unroll
        for (int ks = 0; ks < 4; ks++) {
            uint32_t af[4][4], bf[4][2];
            #pragma unroll
            for (int mi = 0; mi < 4; mi++)
                ldmx4(af[mi], sAb + SWZ((mw + mi * 16 + a_r) * 128 + ks * 32 + a_q));
            #pragma unroll
            for (int ni = 0; ni < 4; ni++)
                ldmx2(bf[ni], sBb + SWZ((nw + ni * 8 + b_r) * 128 + ks * 32 + b_q));
            #pragma unroll
            for (int mi = 0; mi < 4; mi++)
                #pragma unroll
                for (int ni = 0; ni < 4; ni++)
                    mma16816(acc[mi][ni], af[mi], bf[ni]);
        }
        if (t + 1 < nt) {
            __syncthreads();              // everyone done reading buf^1 before overwrite
            store_chunk(t + 1, buf ^ 1);
            __syncthreads();
        }
    }

    // ---- epilogue ----
    #pragma unroll
    for (int mi = 0; mi < 4; mi++) {
        #pragma unroll
        for (int ni = 0; ni < 4; ni++) {
            int m0 = tileM + mw + mi * 16 + (lane >> 2);
            int n0 = tileN + nw + ni * 8 + (lane & 3) * 2;
            float b0 = 0.f, b1 = 0.f;
            if (g.bias) { b0 = g.bias[n0]; b1 = g.bias[n0 + 1]; }
            if (m0 < g.M) {
                float2 o = make_float2(acc[mi][ni][0] + b0, acc[mi][ni][1] + b1);
                *(float2*)(g.C + (size_t)m0 * g.N + n0) = o;
            }
            if (m0 + 8 < g.M) {
                float2 o = make_float2(acc[mi][ni][2] + b0, acc[mi][ni][3] + b1);
                *(float2*)(g.C + (size_t)(m0 + 8) * g.N + n0) = o;
            }
        }
    }
}

// ================= non-GEMM kernels =================
__global__ void eh_proj_kernel(const float* __restrict__ eh, const float* __restrict__ Wn,
                               const float* __restrict__ Wf, float* __restrict__ en,
                               float* __restrict__ ef) {
    int gw   = (blockIdx.x * blockDim.x + threadIdx.x) >> 5;
    int lane = threadIdx.x & 31;
    if (gw >= 2 * B_ * F_) return;
    int which = (gw >= B_ * F_);
    int rem   = which ? gw - B_ * F_ : gw;
    int b = rem >> 9, f = rem & 511;
    const float4* w4 = (const float4*)((which ? Wf : Wn) + (size_t)f * 1024);
    const float4* e4 = (const float4*)(eh + (size_t)b * 1024);
    float s = 0.f;
    for (int k = lane; k < 256; k += 32) {
        float4 a = w4[k], c = e4[k];
        s += a.x * c.x + a.y * c.y + a.z * c.z + a.w * c.w;
    }
    #pragma unroll
    for (int o = 16; o; o >>= 1) s += __shfl_down_sync(0xffffffffu, s, o);
    if (!lane) (which ? ef : en)[rem] = s;
}

__global__ void dot_kernel(const float* __restrict__ X, const float* __restrict__ v,
                           float* __restrict__ out) {
    int gw   = (blockIdx.x * blockDim.x + threadIdx.x) >> 5;
    int lane = threadIdx.x & 31;
    if (gw >= B_ * NN) return;
    int b = gw / NN;
    const float4* x4 = (const float4*)(X + (size_t)gw * F_);
    const float4* v4 = (const float4*)(v + (size_t)b * F_);
    float s = 0.f;
    #pragma unroll
    for (int k = lane; k < 128; k += 32) {
        float4 a = x4[k], c = v4[k];
        s += a.x * c.x + a.y * c.y + a.z * c.z + a.w * c.w;
    }
    #pragma unroll
    for (int o = 16; o; o >>= 1) s += __shfl_down_sync(0xffffffffu, s, o);
    if (!lane) out[gw] = s;
}

__global__ void feat2_kernel(const float* __restrict__ feat, const float* __restrict__ scores,
                             float* __restrict__ feat2) {
    int bi = blockIdx.x;
    int b = bi / NN, i = bi % NN;
    int cnt = min(i + 3, NN - 1) - i + 1;
    float w[4];
    float mx = -1e30f;
    for (int j = 0; j < cnt; j++) { w[j] = scores[b * NN + i + j]; mx = fmaxf(mx, w[j]); }
    float s = 0.f;
    for (int j = 0; j < cnt; j++) { w[j] = expf(w[j] - mx); s += w[j]; }
    float inv = 1.f / s;
    const float4* base = (const float4*)(feat + (size_t)bi * F_);
    float4* o = (float4*)(feat2 + (size_t)bi * F_);
    for (int f = threadIdx.x; f < 128; f += 128) {
        float4 a = make_float4(0.f, 0.f, 0.f, 0.f);
        for (int j = 0; j < cnt; j++) {
            float4 v = base[j * 128 + f];
            a.x += w[j] * v.x; a.y += w[j] * v.y; a.z += w[j] * v.z; a.w += w[j] * v.w;
        }
        a.x *= inv; a.y *= inv; a.z *= inv; a.w *= inv;
        o[f] = a;
    }
}

__global__ void leaf_kernel(const float* __restrict__ feiou, float* __restrict__ h,
                            float* __restrict__ c) {
    size_t idx = (size_t)blockIdx.x * blockDim.x + threadIdx.x;
    if (idx >= (size_t)B_ * 256 * 128) return;
    int f4 = (int)(idx & 127);
    size_t t = idx >> 7;
    int node = 255 + (int)(t % 256);
    int b = (int)(t / 256);
    size_t row = (size_t)b * NN + node;
    const float4* r = (const float4*)(feiou + row * F3);
    float4 ig = r[f4], og = r[128 + f4], ug = r[256 + f4];
    float4 cn, hn;
    cn.x = sigm(ig.x) * fmaxf(ug.x, 0.f); hn.x = sigm(og.x) * tanhf(cn.x);
    cn.y = sigm(ig.y) * fmaxf(ug.y, 0.f); hn.y = sigm(og.y) * tanhf(cn.y);
    cn.z = sigm(ig.z) * fmaxf(ug.z, 0.f); hn.z = sigm(og.z) * tanhf(cn.z);
    cn.w = sigm(ig.w) * fmaxf(ug.w, 0.f); hn.w = sigm(og.w) * tanhf(cn.w);
    ((float4*)(c + row * F_))[f4] = cn;
    ((float4*)(h + row * F_))[f4] = hn;
}

__global__ void combine_kernel(const float* __restrict__ iou_t, const float* __restrict__ f_t,
                               const float* __restrict__ feiou, const float* __restrict__ fefp,
                               float* __restrict__ h, float* __restrict__ c,
                               int start, int cnt) {
    size_t idx = (size_t)blockIdx.x * blockDim.x + threadIdx.x;
    if (idx >= (size_t)B_ * cnt * 128) return;
    int f4 = (int)(idx & 127);
    size_t t = idx >> 7;
    int q = (int)(t % cnt);
    int b = (int)(t / cnt);
    int p = start + q;
    size_t r    = (size_t)b * cnt + q;
    size_t prow = (size_t)b * NN + p;
    const float4* it = (const float4*)(iou_t + r * F3);
    const float4* fi = (const float4*)(feiou + prow * F3);
    float4 ig = it[f4],        og = it[128 + f4],  ug = it[256 + f4];
    float4 i2 = fi[f4],        o2 = fi[128 + f4],  u2 = fi[256 + f4];
    ig.x += i2.x; ig.y += i2.y; ig.z += i2.z; ig.w += i2.w;
    og.x += o2.x; og.y += o2.y; og.z += o2.z; og.w += o2.w;
    ug.x += u2.x; ug.y += u2.y; ug.z += u2.z; ug.w += u2.w;
    float4 fe = ((const float4*)(fefp + ((size_t)b * NP + p) * F_))[f4];
    size_t rf = ((size_t)b * 2 * cnt + 2 * q) * F_;
    float4 fl = ((const float4*)(f_t + rf))[f4];
    float4 fr = ((const float4*)(f_t + rf + F_))[f4];
    size_t cl = ((size_t)b * NN + 2 * p + 1) * F_;
    float4 cL = ((const float4*)(c + cl))[f4];
    float4 cR = ((const float4*)(c + cl + F_))[f4];
    float4 cn, hn;
    {
        float csum = sigm(fl.x + fe.x) * cL.x + sigm(fr.x + fe.x) * cR.x;
        cn.x = sigm(ig.x) * fmaxf(ug.x, 0.f) + csum; hn.x = sigm(og.x) * tanhf(cn.x);
        csum = sigm(fl.y + fe.y) * cL.y + sigm(fr.y + fe.y) * cR.y;
        cn.y = sigm(ig.y) * fmaxf(ug.y, 0.f) + csum; hn.y = sigm(og.y) * tanhf(cn.y);
        csum = sigm(fl.z + fe.z) * cL.z + sigm(fr.z + fe.z) * cR.z;
        cn.z = sigm(ig.z) * fmaxf(ug.z, 0.f) + csum; hn.z = sigm(og.z) * tanhf(cn.z);
        csum = sigm(fl.w + fe.w) * cL.w + sigm(fr.w + fe.w) * cR.w;
        cn.w = sigm(ig.w) * fmaxf(ug.w, 0.f) + csum; hn.w = sigm(og.w) * tanhf(cn.w);
    }
    ((float4*)(c + prow * F_))[f4] = cn;
    ((float4*)(h + prow * F_))[f4] = hn;
}

__global__ void final_kernel(const float* __restrict__ logits, const float* __restrict__ h,
                             float* __restrict__ out) {
    int b = blockIdx.x;
    int t = threadIdx.x;
    __shared__ float sp[512];
    __shared__ float red[17];
    float l = (t < NN) ? logits[b * NN + t] : -1e30f;
    float m = l;
    #pragma unroll
    for (int o = 16; o; o >>= 1) m = fmaxf(m, __shfl_xor_sync(0xffffffffu, m, o));
    if ((t & 31) == 0) red[t >> 5] = m;
    __syncthreads();
    if (t == 0) {
        float mm = red[0];
        for (int i = 1; i < 16; i++) mm = fmaxf(mm, red[i]);
        red[16] = mm;
    }
    __syncthreads();
    float mx = red[16];
    float e = (t < NN) ? expf(l - mx) : 0.f;
    sp[t] = e;
    float s = e;
    #pragma unroll
    for (int o = 16; o; o >>= 1) s += __shfl_xor_sync(0xffffffffu, s, o);
    __syncthreads();
    if ((t & 31) == 0) red[t >> 5] = s;
    __syncthreads();
    if (t == 0) {
        float ss = 0.f;
        for (int i = 0; i < 16; i++) ss += red[i];
        red[16] = 1.f / ss;
    }
    __syncthreads();
    float inv = red[16];
    const float* hb = h + (size_t)b * NN * F_;
    float acc = 0.f;
    for (int i = 0; i < NN; i++) acc += sp[i] * hb[(size_t)i * F_ + t];
    out[b * F_ + t] = acc * inv;
}

// ================= launch =================
extern "C" void kernel_launch(void* const* d_in, const int* in_sizes, int n_in,
                              void* d_out, int out_size) {
    const float* features   = (const float*)d_in[0];
    const float* eh         = (const float*)d_in[5];
    const float* Wn         = (const float*)d_in[6];
    const float* Wf         = (const float*)d_in[7];
    const float* W_U_iou    = (const float*)d_in[8];
    const float* W_U_fe_iou = (const float*)d_in[9];
    const float* b_U_fe_iou = (const float*)d_in[10];
    const float* W_U_f      = (const float*)d_in[11];
    const float* W_U_fe_f   = (const float*)d_in[12];
    const float* b_U_fe_f   = (const float*)d_in[13];
    float* out = (float*)d_out;

    float *p_en, *p_ef, *p_sc, *p_lg, *p_feat2, *p_feiou, *p_fefp, *p_h, *p_c, *p_iou, *p_f;
    __nv_bfloat16 *p_wfeiou, *p_wuiou, *p_wfef, *p_wuf;
    cudaGetSymbolAddress((void**)&p_en,     g_enode);
    cudaGetSymbolAddress((void**)&p_ef,     g_eforw);
    cudaGetSymbolAddress((void**)&p_sc,     g_scores);
    cudaGetSymbolAddress((void**)&p_lg,     g_logits);
    cudaGetSymbolAddress((void**)&p_feat2,  g_feat2);
    cudaGetSymbolAddress((void**)&p_feiou,  g_feiou);
    cudaGetSymbolAddress((void**)&p_fefp,   g_fefp);
    cudaGetSymbolAddress((void**)&p_h,      g_h);
    cudaGetSymbolAddress((void**)&p_c,      g_c);
    cudaGetSymbolAddress((void**)&p_iou,    g_iou_t);
    cudaGetSymbolAddress((void**)&p_f,      g_f_t);
    cudaGetSymbolAddress((void**)&p_wfeiou, g_wfeiou_s);
    cudaGetSymbolAddress((void**)&p_wuiou,  g_wuiou_s);
    cudaGetSymbolAddress((void**)&p_wfef,   g_wfef_s);
    cudaGetSymbolAddress((void**)&p_wuf,    g_wuf_s);

    static int smem_set = 0;
    if (!smem_set) {
        cudaFuncSetAttribute(dual_gemm_mma, cudaFuncAttributeMaxDynamicSharedMemorySize, TC_SMEM);
        smem_set = 1;
    }

    // 0) split weights into bf16 hi/lo
    wsplit_kernel<<<(F3 * 512 + 255) / 256, 256>>>(W_U_fe_iou, p_wfeiou, F3);
    wsplit_kernel<<<(F3 * 512 + 255) / 256, 256>>>(W_U_iou,    p_wuiou,  F3);
    wsplit_kernel<<<(F_ * 512 + 255) / 256, 256>>>(W_U_fe_f,   p_wfef,   F_);
    wsplit_kernel<<<(F_ * 512 + 255) / 256, 256>>>(W_U_f,      p_wuf,    F_);
    // 1) eh projections
    eh_proj_kernel<<<(2 * B_ * F_ * 32 + 255) / 256, 256>>>(eh, Wn, Wf, p_en, p_ef);
    // 2) attention scores + windowed softmax pooling
    dot_kernel<<<(B_ * NN * 32 + 255) / 256, 256>>>(features, p_en, p_sc);
    feat2_kernel<<<B_ * NN, 128>>>(features, p_sc, p_feat2);
    // 3) fe_iou + fe_f (tensor-core dual GEMM)
    {
        GP g0 = { p_feat2, p_wfeiou, b_U_fe_iou, p_feiou, 0, B_ * NN, F3, 0, 1, 0, 12 };
        GP g1 = { p_feat2, p_wfef,   b_U_fe_f,   p_fefp,  1, B_ * NP, F_, 0, NP, NN * F_, 4 };
        dim3 grid(12, (B_ * NN + 127) / 128, 2);
        dual_gemm_mma<<<grid, 256, TC_SMEM>>>(g0, g1);
    }
    // 4) leaves
    leaf_kernel<<<(B_ * 256 * 128 + 255) / 256, 256>>>(p_feiou, p_h, p_c);
    // 5) levels bottom-up
    for (int n = 1; n <= 8; n++) {
        int cnt = 1 << (8 - n);
        int start = cnt - 1;
        GP g0 = { p_h, p_wuiou, nullptr, p_iou, 2, B_ * cnt,     F3, start,         cnt,     NN * F_, 12 };
        GP g1 = { p_h, p_wuf,   nullptr, p_f,   1, 2 * B_ * cnt, F_, 2 * start + 1, 2 * cnt, NN * F_, 4 };
        int y0 = (B_ * cnt + 127) / 128;
        int y1 = (2 * B_ * cnt + 127) / 128;
        dim3 grid(12, y1 > y0 ? y1 : y0, 2);
        dual_gemm_mma<<<grid, 256, TC_SMEM>>>(g0, g1);
        combine_kernel<<<(B_ * cnt * 128 + 255) / 256, 256>>>(p_iou, p_f, p_feiou, p_fefp,
                                                              p_h, p_c, start, cnt);
    }
    // 6) output pooling
    dot_kernel<<<(B_ * NN * 32 + 255) / 256, 256>>>(p_h, p_ef, p_lg);
    final_kernel<<<B_, F_>>>(p_lg, p_h, out);
}

// round 6
// speedup vs baseline: 1.7505x; 1.7505x over previous
#include <cuda_runtime.h>
#include <cuda_bf16.h>
#include <math.h>
#include <stdint.h>

#define B_   32
#define NN   511
#define F_   512
#define NP   255
#define NC   2048   // fused output width: [iou(1536) | f(512)]
#define KS   1024   // split activation width: [hi(512) | lo(512)]

// ---------------- scratch (static device memory) ----------------
__device__ __align__(16) float g_enode [B_*F_];
__device__ __align__(16) float g_eforw [B_*F_];
__device__ __align__(16) float g_scores[B_*NN];
__device__ __align__(16) float g_logits[B_*NN];
__device__ __align__(16) float g_h     [B_*NN*F_];
__device__ __align__(16) float g_c     [B_*NN*F_];
__device__ __align__(16) float g_feiou [(size_t)B_*NN*NC];      // fused fe: iou+f per node
__device__ __align__(16) float g_lvl   [(size_t)B_*256*NC];     // level gemm out (children rows)
__device__ __align__(16) __nv_bfloat16 g_f2s   [(size_t)B_*NN*KS];   // feat2 split
__device__ __align__(16) __nv_bfloat16 g_hsplit[(size_t)B_*NN*KS];   // h split
__device__ __align__(16) __nv_bfloat16 g_wfe   [(size_t)NC*KS];      // [W_fe_iou; W_fe_f] split
__device__ __align__(16) __nv_bfloat16 g_wu    [(size_t)NC*KS];      // [W_iou;   W_f]    split
__device__ __align__(16) float g_biascat[NC];

__device__ __forceinline__ float sigm(float x) { return 1.f / (1.f + expf(-x)); }
__device__ __forceinline__ uint32_t smem_u32(const void* p) {
    uint32_t a;
    asm("{ .reg .u64 t; cvta.to.shared.u64 t, %1; cvt.u32.u64 %0, t; }" : "=r"(a) : "l"(p));
    return a;
}
#define SWZ(o) ((o) ^ (((o) >> 3) & 0x70))
#define CP16(d, s) asm volatile("cp.async.cg.shared.global [%0], [%1], 16;" :: "r"(d), "l"(s))
#define CP_COMMIT() asm volatile("cp.async.commit_group;")
#define CP_WAIT(n)  asm volatile("cp.async.wait_group %0;" :: "n"(n))

__device__ __forceinline__ void ldmx4(uint32_t* r, uint32_t addr) {
    asm volatile("ldmatrix.sync.aligned.m8n8.x4.shared.b16 {%0,%1,%2,%3}, [%4];"
                 : "=r"(r[0]), "=r"(r[1]), "=r"(r[2]), "=r"(r[3]) : "r"(addr));
}
__device__ __forceinline__ void ldmx2(uint32_t* r, uint32_t addr) {
    asm volatile("ldmatrix.sync.aligned.m8n8.x2.shared.b16 {%0,%1}, [%2];"
                 : "=r"(r[0]), "=r"(r[1]) : "r"(addr));
}
__device__ __forceinline__ void mma16816(float* d, const uint32_t* a, const uint32_t* b) {
    asm volatile("mma.sync.aligned.m16n8k16.row.col.f32.bf16.bf16.f32 "
                 "{%0,%1,%2,%3}, {%4,%5,%6,%7}, {%8,%9}, {%0,%1,%2,%3};"
                 : "+f"(d[0]), "+f"(d[1]), "+f"(d[2]), "+f"(d[3])
                 : "r"(a[0]), "r"(a[1]), "r"(a[2]), "r"(a[3]), "r"(b[0]), "r"(b[1]));
}

// ================= weight split into cat buffer: [rbase+r][hi(512)|lo(512)] ========
__global__ void wsplit_cat(const float* __restrict__ W, __nv_bfloat16* __restrict__ O,
                           int rows, int rbase) {
    int idx = blockIdx.x * blockDim.x + threadIdx.x;
    if (idx >= rows * 512) return;
    int r = idx >> 9, k = idx & 511;
    float v = W[idx];
    __nv_bfloat16 hi = __float2bfloat16_rn(v);
    __nv_bfloat16 lo = __float2bfloat16_rn(v - __bfloat162float(hi));
    O[(size_t)(rbase + r) * KS + k]       = hi;
    O[(size_t)(rbase + r) * KS + 512 + k] = lo;
}

__global__ void cat_bias(const float* __restrict__ b_iou, const float* __restrict__ b_f,
                         float* __restrict__ o) {
    int i = blockIdx.x * blockDim.x + threadIdx.x;
    if (i < NC) o[i] = (i < 1536) ? b_iou[i] : b_f[i - 1536];
}

// ================= bf16 HMMA GEMM: C[M,2048] = gather(As)[M,K'=1536] @ Wc^T =========
// A row m: b = m / rows, node = base + m % rows, split row idx = b*NN + node.
// K' chunks c=0..23 of 64; segment c>>3 selects A part {hi,lo,hi}, W part {hi,hi,lo}.
struct GP {
    const __nv_bfloat16* As; const __nv_bfloat16* Wc; const float* bias; float* C;
    int M, rows, base;
};

#define TILE_BYTES 16384
#define GSMEM (4 * TILE_BYTES + 1024)

__global__ void __launch_bounds__(256) gemm_bf16(GP g) {
    extern __shared__ char smem_dyn[];
    const int tileN = blockIdx.x * 128;
    const int tileM = blockIdx.y * 128;
    if (tileM >= g.M) return;

    const uint32_t sb0 = smem_u32(smem_dyn);
    const uint32_t ab  = (sb0 + 1023u) & ~1023u;
    const int tid = threadIdx.x;
    const int wid = tid >> 5, lane = tid & 31;
    const int mw = (wid & 1) * 64;
    const int nw = (wid >> 1) * 32;

    const int row  = tid >> 1;        // 0..127
    const int c16b = (tid & 1) * 4;   // 16B-chunk base within row half
    int row_g = tileM + row; if (row_g >= g.M) row_g = g.M - 1;
    int b = row_g / g.rows, node = g.base + row_g % g.rows;
    const __nv_bfloat16* srcA = g.As + (size_t)(b * NN + node) * KS;
    const __nv_bfloat16* srcB = g.Wc + (size_t)(tileN + row) * KS;

    auto issue = [&](int c, int buf) {
        const int segsel = c >> 3;
        const int aseg = (segsel == 1) ? 512 : 0;
        const int bseg = (segsel == 2) ? 512 : 0;
        const int kb = (c & 7) * 64;
        const uint32_t sA = ab + buf * 2 * TILE_BYTES;
        const uint32_t sB = sA + TILE_BYTES;
        #pragma unroll
        for (int s = 0; s < 4; s++) {
            int cs = c16b + s;
            int eo = kb + cs * 8;
            CP16(sA + SWZ(row * 128 + cs * 16), srcA + aseg + eo);
            CP16(sB + SWZ(row * 128 + cs * 16), srcB + bseg + eo);
        }
        CP_COMMIT();
    };

    float acc[4][4][4] = {};
    const int a_r = lane & 15, a_q = (lane >> 4) * 16;
    const int b_r = lane & 7,  b_q = ((lane >> 3) & 1) * 16;
    const int nt = 24;

    issue(0, 0);
    for (int t = 0; t < nt; t++) {
        if (t + 1 < nt) { issue(t + 1, (t + 1) & 1); CP_WAIT(1); }
        else CP_WAIT(0);
        __syncthreads();
        const uint32_t sAb = ab + (t & 1) * 2 * TILE_BYTES;
        const uint32_t sBb = sAb + TILE_BYTES;
        #pragma unroll
        for (int ks = 0; ks < 4; ks++) {
            uint32_t af[4][4], bf[4][2];
            #pragma unroll
            for (int mi = 0; mi < 4; mi++)
                ldmx4(af[mi], sAb + SWZ((mw + mi * 16 + a_r) * 128 + ks * 32 + a_q));
            #pragma unroll
            for (int ni = 0; ni < 4; ni++)
                ldmx2(bf[ni], sBb + SWZ((nw + ni * 8 + b_r) * 128 + ks * 32 + b_q));
            #pragma unroll
            for (int mi = 0; mi < 4; mi++)
                #pragma unroll
                for (int ni = 0; ni < 4; ni++)
                    mma16816(acc[mi][ni], af[mi], bf[ni]);
        }
        __syncthreads();
    }

    #pragma unroll
    for (int mi = 0; mi < 4; mi++) {
        #pragma unroll
        for (int ni = 0; ni < 4; ni++) {
            int m0 = tileM + mw + mi * 16 + (lane >> 2);
            int n0 = tileN + nw + ni * 8 + (lane & 3) * 2;
            float b0 = 0.f, b1 = 0.f;
            if (g.bias) { b0 = g.bias[n0]; b1 = g.bias[n0 + 1]; }
            if (m0 < g.M)
                *(float2*)(g.C + (size_t)m0 * NC + n0) =
                    make_float2(acc[mi][ni][0] + b0, acc[mi][ni][1] + b1);
            if (m0 + 8 < g.M)
                *(float2*)(g.C + (size_t)(m0 + 8) * NC + n0) =
                    make_float2(acc[mi][ni][2] + b0, acc[mi][ni][3] + b1);
        }
    }
}

// ================= non-GEMM kernels =================
__global__ void eh_proj_kernel(const float* __restrict__ eh, const float* __restrict__ Wn,
                               const float* __restrict__ Wf, float* __restrict__ en,
                               float* __restrict__ ef) {
    int gw   = (blockIdx.x * blockDim.x + threadIdx.x) >> 5;
    int lane = threadIdx.x & 31;
    if (gw >= 2 * B_ * F_) return;
    int which = (gw >= B_ * F_);
    int rem   = which ? gw - B_ * F_ : gw;
    int b = rem >> 9, f = rem & 511;
    const float4* w4 = (const float4*)((which ? Wf : Wn) + (size_t)f * 1024);
    const float4* e4 = (const float4*)(eh + (size_t)b * 1024);
    float s = 0.f;
    for (int k = lane; k < 256; k += 32) {
        float4 a = w4[k], c = e4[k];
        s += a.x * c.x + a.y * c.y + a.z * c.z + a.w * c.w;
    }
    #pragma unroll
    for (int o = 16; o; o >>= 1) s += __shfl_down_sync(0xffffffffu, s, o);
    if (!lane) (which ? ef : en)[rem] = s;
}

__global__ void dot_kernel(const float* __restrict__ X, const float* __restrict__ v,
                           float* __restrict__ out) {
    int gw   = (blockIdx.x * blockDim.x + threadIdx.x) >> 5;
    int lane = threadIdx.x & 31;
    if (gw >= B_ * NN) return;
    int b = gw / NN;
    const float4* x4 = (const float4*)(X + (size_t)gw * F_);
    const float4* v4 = (const float4*)(v + (size_t)b * F_);
    float s = 0.f;
    #pragma unroll
    for (int k = lane; k < 128; k += 32) {
        float4 a = x4[k], c = v4[k];
        s += a.x * c.x + a.y * c.y + a.z * c.z + a.w * c.w;
    }
    #pragma unroll
    for (int o = 16; o; o >>= 1) s += __shfl_down_sync(0xffffffffu, s, o);
    if (!lane) out[gw] = s;
}

// windowed softmax attention -> feat2, written directly as bf16 [hi|lo]
__global__ void feat2s_kernel(const float* __restrict__ feat, const float* __restrict__ scores,
                              __nv_bfloat16* __restrict__ o) {
    int bi = blockIdx.x;
    int b = bi / NN, i = bi % NN;
    int cnt = min(i + 3, NN - 1) - i + 1;
    float w[4];
    float mx = -1e30f;
    for (int j = 0; j < cnt; j++) { w[j] = scores[b * NN + i + j]; mx = fmaxf(mx, w[j]); }
    float s = 0.f;
    for (int j = 0; j < cnt; j++) { w[j] = expf(w[j] - mx); s += w[j]; }
    float inv = 1.f / s;
    const float4* base = (const float4*)(feat + (size_t)bi * F_);
    __nv_bfloat16* orow = o + (size_t)bi * KS;
    int f = threadIdx.x;   // 128 threads, one float4 each
    {
        float4 a = make_float4(0.f, 0.f, 0.f, 0.f);
        for (int j = 0; j < cnt; j++) {
            float4 v = base[j * 128 + f];
            a.x += w[j] * v.x; a.y += w[j] * v.y; a.z += w[j] * v.z; a.w += w[j] * v.w;
        }
        a.x *= inv; a.y *= inv; a.z *= inv; a.w *= inv;
        __nv_bfloat16 h0 = __float2bfloat16_rn(a.x), h1 = __float2bfloat16_rn(a.y);
        __nv_bfloat16 h2 = __float2bfloat16_rn(a.z), h3 = __float2bfloat16_rn(a.w);
        __nv_bfloat16 l0 = __float2bfloat16_rn(a.x - __bfloat162float(h0));
        __nv_bfloat16 l1 = __float2bfloat16_rn(a.y - __bfloat162float(h1));
        __nv_bfloat16 l2 = __float2bfloat16_rn(a.z - __bfloat162float(h2));
        __nv_bfloat16 l3 = __float2bfloat16_rn(a.w - __bfloat162float(h3));
        orow[f * 4 + 0] = h0; orow[f * 4 + 1] = h1; orow[f * 4 + 2] = h2; orow[f * 4 + 3] = h3;
        orow[512 + f * 4 + 0] = l0; orow[512 + f * 4 + 1] = l1;
        orow[512 + f * 4 + 2] = l2; orow[512 + f * 4 + 3] = l3;
    }
}

__device__ __forceinline__ void write_h_split(__nv_bfloat16* hs, size_t row, int f4, float4 hn) {
    __nv_bfloat16* p = hs + row * KS;
    __nv_bfloat16 h0 = __float2bfloat16_rn(hn.x), h1 = __float2bfloat16_rn(hn.y);
    __nv_bfloat16 h2 = __float2bfloat16_rn(hn.z), h3 = __float2bfloat16_rn(hn.w);
    p[f4 * 4 + 0] = h0; p[f4 * 4 + 1] = h1; p[f4 * 4 + 2] = h2; p[f4 * 4 + 3] = h3;
    p[512 + f4 * 4 + 0] = __float2bfloat16_rn(hn.x - __bfloat162float(h0));
    p[512 + f4 * 4 + 1] = __float2bfloat16_rn(hn.y - __bfloat162float(h1));
    p[512 + f4 * 4 + 2] = __float2bfloat16_rn(hn.z - __bfloat162float(h2));
    p[512 + f4 * 4 + 3] = __float2bfloat16_rn(hn.w - __bfloat162float(h3));
}

// leaves (order 0): nodes 255..510
__global__ void leaf_kernel(const float* __restrict__ feiou, float* __restrict__ h,
                            float* __restrict__ c, __nv_bfloat16* __restrict__ hs) {
    size_t idx = (size_t)blockIdx.x * blockDim.x + threadIdx.x;
    if (idx >= (size_t)B_ * 256 * 128) return;
    int f4 = (int)(idx & 127);
    size_t t = idx >> 7;
    int node = 255 + (int)(t % 256);
    int b = (int)(t / 256);
    size_t row = (size_t)b * NN + node;
    const float4* r = (const float4*)(feiou + row * NC);
    float4 ig = r[f4], og = r[128 + f4], ug = r[256 + f4];
    float4 cn, hn;
    cn.x = sigm(ig.x) * fmaxf(ug.x, 0.f); hn.x = sigm(og.x) * tanhf(cn.x);
    cn.y = sigm(ig.y) * fmaxf(ug.y, 0.f); hn.y = sigm(og.y) * tanhf(cn.y);
    cn.z = sigm(ig.z) * fmaxf(ug.z, 0.f); hn.z = sigm(og.z) * tanhf(cn.z);
    cn.w = sigm(ig.w) * fmaxf(ug.w, 0.f); hn.w = sigm(og.w) * tanhf(cn.w);
    ((float4*)(c + row * F_))[f4] = cn;
    ((float4*)(h + row * F_))[f4] = hn;
    write_h_split(hs, row, f4, hn);
}

// per-level combine: sums the two children's GEMM rows
__global__ void combine_kernel(const float* __restrict__ lvl, const float* __restrict__ feiou,
                               float* __restrict__ h, float* __restrict__ c,
                               __nv_bfloat16* __restrict__ hs, int start, int cnt) {
    size_t idx = (size_t)blockIdx.x * blockDim.x + threadIdx.x;
    if (idx >= (size_t)B_ * cnt * 128) return;
    int f4 = (int)(idx & 127);
    size_t t = idx >> 7;
    int q = (int)(t % cnt);
    int b = (int)(t / cnt);
    int p = start + q;
    size_t prow = (size_t)b * NN + p;
    const float4* tL = (const float4*)(lvl + ((size_t)b * 2 * cnt + 2 * q) * NC);
    const float4* tR = tL + (NC / 4);
    const float4* fi = (const float4*)(feiou + prow * NC);
    float4 igL = tL[f4],       igR = tR[f4],       ig2 = fi[f4];
    float4 ogL = tL[128 + f4], ogR = tR[128 + f4], og2 = fi[128 + f4];
    float4 ugL = tL[256 + f4], ugR = tR[256 + f4], ug2 = fi[256 + f4];
    float4 fe  = fi[384 + f4];
    float4 fl  = tL[384 + f4], fr = tR[384 + f4];
    size_t cl = ((size_t)b * NN + 2 * p + 1) * F_;
    float4 cL = ((const float4*)(c + cl))[f4];
    float4 cR = ((const float4*)(c + cl + F_))[f4];
    float4 cn, hn;
    {
        float ig = igL.x + igR.x + ig2.x, og = ogL.x + ogR.x + og2.x, ug = ugL.x + ugR.x + ug2.x;
        float cs = sigm(fl.x + fe.x) * cL.x + sigm(fr.x + fe.x) * cR.x;
        cn.x = sigm(ig) * fmaxf(ug, 0.f) + cs; hn.x = sigm(og) * tanhf(cn.x);
        ig = igL.y + igR.y + ig2.y; og = ogL.y + ogR.y + og2.y; ug = ugL.y + ugR.y + ug2.y;
        cs = sigm(fl.y + fe.y) * cL.y + sigm(fr.y + fe.y) * cR.y;
        cn.y = sigm(ig) * fmaxf(ug, 0.f) + cs; hn.y = sigm(og) * tanhf(cn.y);
        ig = igL.z + igR.z + ig2.z; og = ogL.z + ogR.z + og2.z; ug = ugL.z + ugR.z + ug2.z;
        cs = sigm(fl.z + fe.z) * cL.z + sigm(fr.z + fe.z) * cR.z;
        cn.z = sigm(ig) * fmaxf(ug, 0.f) + cs; hn.z = sigm(og) * tanhf(cn.z);
        ig = igL.w + igR.w + ig2.w; og = ogL.w + ogR.w + og2.w; ug = ugL.w + ugR.w + ug2.w;
        cs = sigm(fl.w + fe.w) * cL.w + sigm(fr.w + fe.w) * cR.w;
        cn.w = sigm(ig) * fmaxf(ug, 0.f) + cs; hn.w = sigm(og) * tanhf(cn.w);
    }
    ((float4*)(c + prow * F_))[f4] = cn;
    ((float4*)(h + prow * F_))[f4] = hn;
    write_h_split(hs, prow, f4, hn);
}

__global__ void final_kernel(const float* __restrict__ logits, const float* __restrict__ h,
                             float* __restrict__ out) {
    int b = blockIdx.x;
    int t = threadIdx.x;
    __shared__ float sp[512];
    __shared__ float red[17];
    float l = (t < NN) ? logits[b * NN + t] : -1e30f;
    float m = l;
    #pragma unroll
    for (int o = 16; o; o >>= 1) m = fmaxf(m, __shfl_xor_sync(0xffffffffu, m, o));
    if ((t & 31) == 0) red[t >> 5] = m;
    __syncthreads();
    if (t == 0) {
        float mm = red[0];
        for (int i = 1; i < 16; i++) mm = fmaxf(mm, red[i]);
        red[16] = mm;
    }
    __syncthreads();
    float mx = red[16];
    float e = (t < NN) ? expf(l - mx) : 0.f;
    sp[t] = e;
    float s = e;
    #pragma unroll
    for (int o = 16; o; o >>= 1) s += __shfl_xor_sync(0xffffffffu, s, o);
    __syncthreads();
    if ((t & 31) == 0) red[t >> 5] = s;
    __syncthreads();
    if (t == 0) {
        float ss = 0.f;
        for (int i = 0; i < 16; i++) ss += red[i];
        red[16] = 1.f / ss;
    }
    __syncthreads();
    float inv = red[16];
    const float* hb = h + (size_t)b * NN * F_;
    float acc = 0.f;
    for (int i = 0; i < NN; i++) acc += sp[i] * hb[(size_t)i * F_ + t];
    out[b * F_ + t] = acc * inv;
}

// ================= launch =================
extern "C" void kernel_launch(void* const* d_in, const int* in_sizes, int n_in,
                              void* d_out, int out_size) {
    const float* features   = (const float*)d_in[0];
    const float* eh         = (const float*)d_in[5];
    const float* Wn         = (const float*)d_in[6];
    const float* Wf         = (const float*)d_in[7];
    const float* W_U_iou    = (const float*)d_in[8];
    const float* W_U_fe_iou = (const float*)d_in[9];
    const float* b_U_fe_iou = (const float*)d_in[10];
    const float* W_U_f      = (const float*)d_in[11];
    const float* W_U_fe_f   = (const float*)d_in[12];
    const float* b_U_fe_f   = (const float*)d_in[13];
    float* out = (float*)d_out;

    float *p_en, *p_ef, *p_sc, *p_lg, *p_h, *p_c, *p_feiou, *p_lvl, *p_bias;
    __nv_bfloat16 *p_f2s, *p_hs, *p_wfe, *p_wu;
    cudaGetSymbolAddress((void**)&p_en,    g_enode);
    cudaGetSymbolAddress((void**)&p_ef,    g_eforw);
    cudaGetSymbolAddress((void**)&p_sc,    g_scores);
    cudaGetSymbolAddress((void**)&p_lg,    g_logits);
    cudaGetSymbolAddress((void**)&p_h,     g_h);
    cudaGetSymbolAddress((void**)&p_c,     g_c);
    cudaGetSymbolAddress((void**)&p_feiou, g_feiou);
    cudaGetSymbolAddress((void**)&p_lvl,   g_lvl);
    cudaGetSymbolAddress((void**)&p_bias,  g_biascat);
    cudaGetSymbolAddress((void**)&p_f2s,   g_f2s);
    cudaGetSymbolAddress((void**)&p_hs,    g_hsplit);
    cudaGetSymbolAddress((void**)&p_wfe,   g_wfe);
    cudaGetSymbolAddress((void**)&p_wu,    g_wu);

    static int smem_set = 0;
    if (!smem_set) {
        cudaFuncSetAttribute(gemm_bf16, cudaFuncAttributeMaxDynamicSharedMemorySize, GSMEM);
        smem_set = 1;
    }

    // 0) split + concat weights / bias
    wsplit_cat<<<(1536 * 512 + 255) / 256, 256>>>(W_U_fe_iou, p_wfe, 1536, 0);
    wsplit_cat<<<(512 * 512 + 255) / 256, 256>>>(W_U_fe_f,    p_wfe, 512, 1536);
    wsplit_cat<<<(1536 * 512 + 255) / 256, 256>>>(W_U_iou,    p_wu,  1536, 0);
    wsplit_cat<<<(512 * 512 + 255) / 256, 256>>>(W_U_f,       p_wu,  512, 1536);
    cat_bias<<<(NC + 255) / 256, 256>>>(b_U_fe_iou, b_U_fe_f, p_bias);
    // 1) eh projections + attention
    eh_proj_kernel<<<(2 * B_ * F_ * 32 + 255) / 256, 256>>>(eh, Wn, Wf, p_en, p_ef);
    dot_kernel<<<(B_ * NN * 32 + 255) / 256, 256>>>(features, p_en, p_sc);
    feat2s_kernel<<<B_ * NN, 128>>>(features, p_sc, p_f2s);
    // 2) fused fe GEMM: all nodes x [iou | f]
    {
        GP g = { p_f2s, p_wfe, p_bias, p_feiou, B_ * NN, NN, 0 };
        dim3 grid(NC / 128, (B_ * NN + 127) / 128);
        gemm_bf16<<<grid, 256, GSMEM>>>(g);
    }
    // 3) leaves
    leaf_kernel<<<(B_ * 256 * 128 + 255) / 256, 256>>>(p_feiou, p_h, p_c, p_hs);
    // 4) levels bottom-up: one GEMM over the contiguous child range + combine
    for (int n = 1; n <= 8; n++) {
        int cnt = 1 << (8 - n);          // parents per batch
        int start = cnt - 1;
        int rows = 2 * cnt;              // children per batch (contiguous: 2*start+1 ..)
        GP g = { p_hs, p_wu, nullptr, p_lvl, B_ * rows, rows, 2 * start + 1 };
        dim3 grid(NC / 128, (B_ * rows + 127) / 128);
        gemm_bf16<<<grid, 256, GSMEM>>>(g);
        combine_kernel<<<(B_ * cnt * 128 + 255) / 256, 256>>>(p_lvl, p_feiou,
                                                              p_h, p_c, p_hs, start, cnt);
    }
    // 5) output pooling
    dot_kernel<<<(B_ * NN * 32 + 255) / 256, 256>>>(p_h, p_ef, p_lg);
    final_kernel<<<B_, F_>>>(p_lg, p_h, out);
}

// round 7
// speedup vs baseline: 2.0413x; 1.1661x over previous
#include <cuda_runtime.h>
#include <cuda_bf16.h>
#include <math.h>
#include <stdint.h>

#define B_   32
#define NN   511
#define F_   512
#define NP   255
#define NC   2048   // fused output width: [iou(1536) | f(512)]
#define KS   1024   // split activation width: [hi(512) | lo(512)]

// ---------------- scratch (static device memory) ----------------
__device__ __align__(16) float g_enode [B_*F_];
__device__ __align__(16) float g_eforw [B_*F_];
__device__ __align__(16) float g_logits[B_*NN];
__device__ __align__(16) float g_h     [B_*NN*F_];
__device__ __align__(16) float g_c     [B_*NN*F_];
__device__ __align__(16) float g_feiou [(size_t)B_*NN*NC];
__device__ __align__(16) float g_lvl   [(size_t)B_*256*NC];
__device__ __align__(16) __nv_bfloat16 g_f2s   [(size_t)B_*NN*KS];
__device__ __align__(16) __nv_bfloat16 g_hsplit[(size_t)B_*NN*KS];
__device__ __align__(16) __nv_bfloat16 g_wfe   [(size_t)NC*KS];
__device__ __align__(16) __nv_bfloat16 g_wu    [(size_t)NC*KS];
__device__ __align__(16) float g_biascat[NC];

__device__ __forceinline__ float sigm(float x) { return 1.f / (1.f + expf(-x)); }
__device__ __forceinline__ uint32_t smem_u32(const void* p) {
    uint32_t a;
    asm("{ .reg .u64 t; cvta.to.shared.u64 t, %1; cvt.u32.u64 %0, t; }" : "=r"(a) : "l"(p));
    return a;
}
#define SWZ(o) ((o) ^ (((o) >> 3) & 0x70))
#define CP16(d, s) asm volatile("cp.async.cg.shared.global [%0], [%1], 16;" :: "r"(d), "l"(s))
#define CP_COMMIT() asm volatile("cp.async.commit_group;")
#define CP_WAIT(n)  asm volatile("cp.async.wait_group %0;" :: "n"(n))

__device__ __forceinline__ void ldmx4(uint32_t* r, uint32_t addr) {
    asm volatile("ldmatrix.sync.aligned.m8n8.x4.shared.b16 {%0,%1,%2,%3}, [%4];"
                 : "=r"(r[0]), "=r"(r[1]), "=r"(r[2]), "=r"(r[3]) : "r"(addr));
}
__device__ __forceinline__ void ldmx2(uint32_t* r, uint32_t addr) {
    asm volatile("ldmatrix.sync.aligned.m8n8.x2.shared.b16 {%0,%1}, [%2];"
                 : "=r"(r[0]), "=r"(r[1]) : "r"(addr));
}
__device__ __forceinline__ void mma16816(float* d, const uint32_t* a, const uint32_t* b) {
    asm volatile("mma.sync.aligned.m16n8k16.row.col.f32.bf16.bf16.f32 "
                 "{%0,%1,%2,%3}, {%4,%5,%6,%7}, {%8,%9}, {%0,%1,%2,%3};"
                 : "+f"(d[0]), "+f"(d[1]), "+f"(d[2]), "+f"(d[3])
                 : "r"(a[0]), "r"(a[1]), "r"(a[2]), "r"(a[3]), "r"(b[0]), "r"(b[1]));
}

// ================= all weights split in ONE launch ================
// layout target: O[(rbase+r)*KS + {k | 512+k}] = {hi | lo}
__global__ void wsplit_all(const float* __restrict__ Wfeiou, const float* __restrict__ Wfef,
                           const float* __restrict__ Wuiou,  const float* __restrict__ Wuf,
                           __nv_bfloat16* __restrict__ Ofe, __nv_bfloat16* __restrict__ Ou,
                           const float* __restrict__ b_iou, const float* __restrict__ b_f,
                           float* __restrict__ bias) {
    int idx = blockIdx.x * blockDim.x + threadIdx.x;
    if (idx < NC) bias[idx] = (idx < 1536) ? b_iou[idx] : b_f[idx - 1536];
    if (idx >= 2 * NC * 512) return;
    int which = idx >= NC * 512;           // 0: fe pair, 1: u pair
    int rem = which ? idx - NC * 512 : idx;
    int r = rem >> 9, k = rem & 511;
    const float* W = which ? (r < 1536 ? Wuiou : Wuf) : (r < 1536 ? Wfeiou : Wfef);
    int rl = (r < 1536) ? r : r - 1536;
    float v = W[(size_t)rl * 512 + k];
    __nv_bfloat16 hi = __float2bfloat16_rn(v);
    __nv_bfloat16 lo = __float2bfloat16_rn(v - __bfloat162float(hi));
    __nv_bfloat16* O = which ? Ou : Ofe;
    O[(size_t)r * KS + k]       = hi;
    O[(size_t)r * KS + 512 + k] = lo;
}

// ================= bf16 HMMA GEMM, 3-stage cp.async pipeline =================
struct GP {
    const __nv_bfloat16* As; const __nv_bfloat16* Wc; const float* bias; float* C;
    int M, rows, base;
};

#define TILE_BYTES 16384
#define NSTAGE 3
#define GSMEM (NSTAGE * 2 * TILE_BYTES + 1024)

__global__ void __launch_bounds__(256) gemm_bf16(GP g) {
    extern __shared__ char smem_dyn[];
    const int tileN = blockIdx.x * 128;
    const int tileM = blockIdx.y * 128;
    if (tileM >= g.M) return;

    const uint32_t sb0 = smem_u32(smem_dyn);
    const uint32_t ab  = (sb0 + 1023u) & ~1023u;
    const int tid = threadIdx.x;
    const int wid = tid >> 5, lane = tid & 31;
    const int mw = (wid & 1) * 64;
    const int nw = (wid >> 1) * 32;

    const int row  = tid >> 1;
    const int c16b = (tid & 1) * 4;
    int row_g = tileM + row; if (row_g >= g.M) row_g = g.M - 1;
    int b = row_g / g.rows, node = g.base + row_g % g.rows;
    const __nv_bfloat16* srcA = g.As + (size_t)(b * NN + node) * KS;
    const __nv_bfloat16* srcB = g.Wc + (size_t)(tileN + row) * KS;

    auto issue = [&](int c, int buf) {
        const int segsel = c >> 3;
        const int aseg = (segsel == 1) ? 512 : 0;
        const int bseg = (segsel == 2) ? 512 : 0;
        const int kb = (c & 7) * 64;
        const uint32_t sA = ab + buf * 2 * TILE_BYTES;
        const uint32_t sB = sA + TILE_BYTES;
        #pragma unroll
        for (int s = 0; s < 4; s++) {
            int cs = c16b + s;
            int eo = kb + cs * 8;
            CP16(sA + SWZ(row * 128 + cs * 16), srcA + aseg + eo);
            CP16(sB + SWZ(row * 128 + cs * 16), srcB + bseg + eo);
        }
        CP_COMMIT();
    };

    float acc[4][4][4] = {};
    const int a_r = lane & 15, a_q = (lane >> 4) * 16;
    const int b_r = lane & 7,  b_q = ((lane >> 3) & 1) * 16;
    const int nt = 24;

    issue(0, 0);
    issue(1, 1);
    int buf = 0;
    for (int t = 0; t < nt; t++) {
        if (t + 1 < nt) CP_WAIT(1); else CP_WAIT(0);
        __syncthreads();
        const uint32_t sAb = ab + buf * 2 * TILE_BYTES;
        const uint32_t sBb = sAb + TILE_BYTES;
        #pragma unroll
        for (int ks = 0; ks < 4; ks++) {
            uint32_t af[4][4], bf[4][2];
            #pragma unroll
            for (int mi = 0; mi < 4; mi++)
                ldmx4(af[mi], sAb + SWZ((mw + mi * 16 + a_r) * 128 + ks * 32 + a_q));
            #pragma unroll
            for (int ni = 0; ni < 4; ni++)
                ldmx2(bf[ni], sBb + SWZ((nw + ni * 8 + b_r) * 128 + ks * 32 + b_q));
            #pragma unroll
            for (int mi = 0; mi < 4; mi++)
                #pragma unroll
                for (int ni = 0; ni < 4; ni++)
                    mma16816(acc[mi][ni], af[mi], bf[ni]);
        }
        if (t + 2 < nt) issue(t + 2, (t + 2) % NSTAGE);
        buf = (buf + 1 == NSTAGE) ? 0 : buf + 1;
    }

    #pragma unroll
    for (int mi = 0; mi < 4; mi++) {
        #pragma unroll
        for (int ni = 0; ni < 4; ni++) {
            int m0 = tileM + mw + mi * 16 + (lane >> 2);
            int n0 = tileN + nw + ni * 8 + (lane & 3) * 2;
            float b0 = 0.f, b1 = 0.f;
            if (g.bias) { b0 = g.bias[n0]; b1 = g.bias[n0 + 1]; }
            if (m0 < g.M)
                *(float2*)(g.C + (size_t)m0 * NC + n0) =
                    make_float2(acc[mi][ni][0] + b0, acc[mi][ni][1] + b1);
            if (m0 + 8 < g.M)
                *(float2*)(g.C + (size_t)(m0 + 8) * NC + n0) =
                    make_float2(acc[mi][ni][2] + b0, acc[mi][ni][3] + b1);
        }
    }
}

// ================= non-GEMM kernels =================
__global__ void eh_proj_kernel(const float* __restrict__ eh, const float* __restrict__ Wn,
                               const float* __restrict__ Wf, float* __restrict__ en,
                               float* __restrict__ ef) {
    int gw   = (blockIdx.x * blockDim.x + threadIdx.x) >> 5;
    int lane = threadIdx.x & 31;
    if (gw >= 2 * B_ * F_) return;
    int which = (gw >= B_ * F_);
    int rem   = which ? gw - B_ * F_ : gw;
    int b = rem >> 9, f = rem & 511;
    const float4* w4 = (const float4*)((which ? Wf : Wn) + (size_t)f * 1024);
    const float4* e4 = (const float4*)(eh + (size_t)b * 1024);
    float s = 0.f;
    for (int k = lane; k < 256; k += 32) {
        float4 a = w4[k], c = e4[k];
        s += a.x * c.x + a.y * c.y + a.z * c.z + a.w * c.w;
    }
    #pragma unroll
    for (int o = 16; o; o >>= 1) s += __shfl_down_sync(0xffffffffu, s, o);
    if (!lane) (which ? ef : en)[rem] = s;
}

__global__ void dot_kernel(const float* __restrict__ X, const float* __restrict__ v,
                           float* __restrict__ out) {
    int gw   = (blockIdx.x * blockDim.x + threadIdx.x) >> 5;
    int lane = threadIdx.x & 31;
    if (gw >= B_ * NN) return;
    int b = gw / NN;
    const float4* x4 = (const float4*)(X + (size_t)gw * F_);
    const float4* v4 = (const float4*)(v + (size_t)b * F_);
    float s = 0.f;
    #pragma unroll
    for (int k = lane; k < 128; k += 32) {
        float4 a = x4[k], c = v4[k];
        s += a.x * c.x + a.y * c.y + a.z * c.z + a.w * c.w;
    }
    #pragma unroll
    for (int o = 16; o; o >>= 1) s += __shfl_down_sync(0xffffffffu, s, o);
    if (!lane) out[gw] = s;
}

// windowed attention fused: computes its own 4 scores, softmax, pooling, bf16 split out
__global__ void feat2s_kernel(const float* __restrict__ feat, const float* __restrict__ en,
                              __nv_bfloat16* __restrict__ o) {
    int bi = blockIdx.x;
    int b = bi / NN, i = bi % NN;
    int cnt = min(i + 3, NN - 1) - i + 1;
    __shared__ float sw[4];
    int t = threadIdx.x;          // 128 threads
    // scores: warp j (j<cnt) computes dot(feat[b,i+j], en[b])
    int wj = t >> 5, lane = t & 31;
    if (wj < cnt) {
        const float4* x4 = (const float4*)(feat + ((size_t)bi + wj) * F_);
        const float4* v4 = (const float4*)(en + (size_t)b * F_);
        float s = 0.f;
        #pragma unroll
        for (int k = lane; k < 128; k += 32) {
            float4 a = x4[k], c = v4[k];
            s += a.x * c.x + a.y * c.y + a.z * c.z + a.w * c.w;
        }
        #pragma unroll
        for (int off = 16; off; off >>= 1) s += __shfl_down_sync(0xffffffffu, s, off);
        if (!lane) sw[wj] = s;
    }
    __syncthreads();
    float w[4];
    float mx = -1e30f;
    for (int j = 0; j < cnt; j++) { w[j] = sw[j]; mx = fmaxf(mx, w[j]); }
    float ssum = 0.f;
    for (int j = 0; j < cnt; j++) { w[j] = expf(w[j] - mx); ssum += w[j]; }
    float inv = 1.f / ssum;
    const float4* base = (const float4*)(feat + (size_t)bi * F_);
    __nv_bfloat16* orow = o + (size_t)bi * KS;
    {
        int f = t;
        float4 a = make_float4(0.f, 0.f, 0.f, 0.f);
        for (int j = 0; j < cnt; j++) {
            float4 v = base[j * 128 + f];
            a.x += w[j] * v.x; a.y += w[j] * v.y; a.z += w[j] * v.z; a.w += w[j] * v.w;
        }
        a.x *= inv; a.y *= inv; a.z *= inv; a.w *= inv;
        __nv_bfloat16 h0 = __float2bfloat16_rn(a.x), h1 = __float2bfloat16_rn(a.y);
        __nv_bfloat16 h2 = __float2bfloat16_rn(a.z), h3 = __float2bfloat16_rn(a.w);
        orow[f * 4 + 0] = h0; orow[f * 4 + 1] = h1; orow[f * 4 + 2] = h2; orow[f * 4 + 3] = h3;
        orow[512 + f * 4 + 0] = __float2bfloat16_rn(a.x - __bfloat162float(h0));
        orow[512 + f * 4 + 1] = __float2bfloat16_rn(a.y - __bfloat162float(h1));
        orow[512 + f * 4 + 2] = __float2bfloat16_rn(a.z - __bfloat162float(h2));
        orow[512 + f * 4 + 3] = __float2bfloat16_rn(a.w - __bfloat162float(h3));
    }
}

__device__ __forceinline__ void write_h_split(__nv_bfloat16* hs, size_t row, int f4, float4 hn) {
    __nv_bfloat16* p = hs + row * KS;
    __nv_bfloat16 h0 = __float2bfloat16_rn(hn.x), h1 = __float2bfloat16_rn(hn.y);
    __nv_bfloat16 h2 = __float2bfloat16_rn(hn.z), h3 = __float2bfloat16_rn(hn.w);
    p[f4 * 4 + 0] = h0; p[f4 * 4 + 1] = h1; p[f4 * 4 + 2] = h2; p[f4 * 4 + 3] = h3;
    p[512 + f4 * 4 + 0] = __float2bfloat16_rn(hn.x - __bfloat162float(h0));
    p[512 + f4 * 4 + 1] = __float2bfloat16_rn(hn.y - __bfloat162float(h1));
    p[512 + f4 * 4 + 2] = __float2bfloat16_rn(hn.z - __bfloat162float(h2));
    p[512 + f4 * 4 + 3] = __float2bfloat16_rn(hn.w - __bfloat162float(h3));
}

__global__ void leaf_kernel(const float* __restrict__ feiou, float* __restrict__ h,
                            float* __restrict__ c, __nv_bfloat16* __restrict__ hs) {
    size_t idx = (size_t)blockIdx.x * blockDim.x + threadIdx.x;
    if (idx >= (size_t)B_ * 256 * 128) return;
    int f4 = (int)(idx & 127);
    size_t t = idx >> 7;
    int node = 255 + (int)(t % 256);
    int b = (int)(t / 256);
    size_t row = (size_t)b * NN + node;
    const float4* r = (const float4*)(feiou + row * NC);
    float4 ig = r[f4], og = r[128 + f4], ug = r[256 + f4];
    float4 cn, hn;
    cn.x = sigm(ig.x) * fmaxf(ug.x, 0.f); hn.x = sigm(og.x) * tanhf(cn.x);
    cn.y = sigm(ig.y) * fmaxf(ug.y, 0.f); hn.y = sigm(og.y) * tanhf(cn.y);
    cn.z = sigm(ig.z) * fmaxf(ug.z, 0.f); hn.z = sigm(og.z) * tanhf(cn.z);
    cn.w = sigm(ig.w) * fmaxf(ug.w, 0.f); hn.w = sigm(og.w) * tanhf(cn.w);
    ((float4*)(c + row * F_))[f4] = cn;
    ((float4*)(h + row * F_))[f4] = hn;
    write_h_split(hs, row, f4, hn);
}

__global__ void combine_kernel(const float* __restrict__ lvl, const float* __restrict__ feiou,
                               float* __restrict__ h, float* __restrict__ c,
                               __nv_bfloat16* __restrict__ hs, int start, int cnt) {
    size_t idx = (size_t)blockIdx.x * blockDim.x + threadIdx.x;
    if (idx >= (size_t)B_ * cnt * 128) return;
    int f4 = (int)(idx & 127);
    size_t t = idx >> 7;
    int q = (int)(t % cnt);
    int b = (int)(t / cnt);
    int p = start + q;
    size_t prow = (size_t)b * NN + p;
    const float4* tL = (const float4*)(lvl + ((size_t)b * 2 * cnt + 2 * q) * NC);
    const float4* tR = tL + (NC / 4);
    const float4* fi = (const float4*)(feiou + prow * NC);
    float4 igL = tL[f4],       igR = tR[f4],       ig2 = fi[f4];
    float4 ogL = tL[128 + f4], ogR = tR[128 + f4], og2 = fi[128 + f4];
    float4 ugL = tL[256 + f4], ugR = tR[256 + f4], ug2 = fi[256 + f4];
    float4 fe  = fi[384 + f4];
    float4 fl  = tL[384 + f4], fr = tR[384 + f4];
    size_t cl = ((size_t)b * NN + 2 * p + 1) * F_;
    float4 cL = ((const float4*)(c + cl))[f4];
    float4 cR = ((const float4*)(c + cl + F_))[f4];
    float4 cn, hn;
    {
        float ig = igL.x + igR.x + ig2.x, og = ogL.x + ogR.x + og2.x, ug = ugL.x + ugR.x + ug2.x;
        float cs = sigm(fl.x + fe.x) * cL.x + sigm(fr.x + fe.x) * cR.x;
        cn.x = sigm(ig) * fmaxf(ug, 0.f) + cs; hn.x = sigm(og) * tanhf(cn.x);
        ig = igL.y + igR.y + ig2.y; og = ogL.y + ogR.y + og2.y; ug = ugL.y + ugR.y + ug2.y;
        cs = sigm(fl.y + fe.y) * cL.y + sigm(fr.y + fe.y) * cR.y;
        cn.y = sigm(ig) * fmaxf(ug, 0.f) + cs; hn.y = sigm(og) * tanhf(cn.y);
        ig = igL.z + igR.z + ig2.z; og = ogL.z + ogR.z + og2.z; ug = ugL.z + ugR.z + ug2.z;
        cs = sigm(fl.z + fe.z) * cL.z + sigm(fr.z + fe.z) * cR.z;
        cn.z = sigm(ig) * fmaxf(ug, 0.f) + cs; hn.z = sigm(og) * tanhf(cn.z);
        ig = igL.w + igR.w + ig2.w; og = ogL.w + ogR.w + og2.w; ug = ugL.w + ugR.w + ug2.w;
        cs = sigm(fl.w + fe.w) * cL.w + sigm(fr.w + fe.w) * cR.w;
        cn.w = sigm(ig) * fmaxf(ug, 0.f) + cs; hn.w = sigm(og) * tanhf(cn.w);
    }
    ((float4*)(c + prow * F_))[f4] = cn;
    ((float4*)(h + prow * F_))[f4] = hn;
    write_h_split(hs, prow, f4, hn);
}

__global__ void final_kernel(const float* __restrict__ logits, const float* __restrict__ h,
                             float* __restrict__ out) {
    int b = blockIdx.x;
    int t = threadIdx.x;
    __shared__ float sp[512];
    __shared__ float red[17];
    float l = (t < NN) ? logits[b * NN + t] : -1e30f;
    float m = l;
    #pragma unroll
    for (int o = 16; o; o >>= 1) m = fmaxf(m, __shfl_xor_sync(0xffffffffu, m, o));
    if ((t & 31) == 0) red[t >> 5] = m;
    __syncthreads();
    if (t == 0) {
        float mm = red[0];
        for (int i = 1; i < 16; i++) mm = fmaxf(mm, red[i]);
        red[16] = mm;
    }
    __syncthreads();
    float mx = red[16];
    float e = (t < NN) ? expf(l - mx) : 0.f;
    sp[t] = e;
    float s = e;
    #pragma unroll
    for (int o = 16; o; o >>= 1) s += __shfl_xor_sync(0xffffffffu, s, o);
    __syncthreads();
    if ((t & 31) == 0) red[t >> 5] = s;
    __syncthreads();
    if (t == 0) {
        float ss = 0.f;
        for (int i = 0; i < 16; i++) ss += red[i];
        red[16] = 1.f / ss;
    }
    __syncthreads();
    float inv = red[16];
    const float* hb = h + (size_t)b * NN * F_;
    float acc = 0.f;
    for (int i = 0; i < NN; i++) acc += sp[i] * hb[(size_t)i * F_ + t];
    out[b * F_ + t] = acc * inv;
}

// ================= launch =================
extern "C" void kernel_launch(void* const* d_in, const int* in_sizes, int n_in,
                              void* d_out, int out_size) {
    const float* features   = (const float*)d_in[0];
    const float* eh         = (const float*)d_in[5];
    const float* Wn         = (const float*)d_in[6];
    const float* Wf         = (const float*)d_in[7];
    const float* W_U_iou    = (const float*)d_in[8];
    const float* W_U_fe_iou = (const float*)d_in[9];
    const float* b_U_fe_iou = (const float*)d_in[10];
    const float* W_U_f      = (const float*)d_in[11];
    const float* W_U_fe_f   = (const float*)d_in[12];
    const float* b_U_fe_f   = (const float*)d_in[13];
    float* out = (float*)d_out;

    float *p_en, *p_ef, *p_lg, *p_h, *p_c, *p_feiou, *p_lvl, *p_bias;
    __nv_bfloat16 *p_f2s, *p_hs, *p_wfe, *p_wu;
    cudaGetSymbolAddress((void**)&p_en,    g_enode);
    cudaGetSymbolAddress((void**)&p_ef,    g_eforw);
    cudaGetSymbolAddress((void**)&p_lg,    g_logits);
    cudaGetSymbolAddress((void**)&p_h,     g_h);
    cudaGetSymbolAddress((void**)&p_c,     g_c);
    cudaGetSymbolAddress((void**)&p_feiou, g_feiou);
    cudaGetSymbolAddress((void**)&p_lvl,   g_lvl);
    cudaGetSymbolAddress((void**)&p_bias,  g_biascat);
    cudaGetSymbolAddress((void**)&p_f2s,   g_f2s);
    cudaGetSymbolAddress((void**)&p_hs,    g_hsplit);
    cudaGetSymbolAddress((void**)&p_wfe,   g_wfe);
    cudaGetSymbolAddress((void**)&p_wu,    g_wu);

    static int smem_set = 0;
    if (!smem_set) {
        cudaFuncSetAttribute(gemm_bf16, cudaFuncAttributeMaxDynamicSharedMemorySize, GSMEM);
        smem_set = 1;
    }

    // 0) split all weights + bias (one launch)
    wsplit_all<<<(2 * NC * 512 + 255) / 256, 256>>>(W_U_fe_iou, W_U_fe_f, W_U_iou, W_U_f,
                                                    p_wfe, p_wu, b_U_fe_iou, b_U_fe_f, p_bias);
    // 1) eh projections + fused attention
    eh_proj_kernel<<<(2 * B_ * F_ * 32 + 255) / 256, 256>>>(eh, Wn, Wf, p_en, p_ef);
    feat2s_kernel<<<B_ * NN, 128>>>(features, p_en, p_f2s);
    // 2) fused fe GEMM
    {
        GP g = { p_f2s, p_wfe, p_bias, p_feiou, B_ * NN, NN, 0 };
        dim3 grid(NC / 128, (B_ * NN + 127) / 128);
        gemm_bf16<<<grid, 256, GSMEM>>>(g);
    }
    // 3) leaves
    leaf_kernel<<<(B_ * 256 * 128 + 255) / 256, 256>>>(p_feiou, p_h, p_c, p_hs);
    // 4) levels bottom-up
    for (int n = 1; n <= 8; n++) {
        int cnt = 1 << (8 - n);
        int start = cnt - 1;
        int rows = 2 * cnt;
        GP g = { p_hs, p_wu, nullptr, p_lvl, B_ * rows, rows, 2 * start + 1 };
        dim3 grid(NC / 128, (B_ * rows + 127) / 128);
        gemm_bf16<<<grid, 256, GSMEM>>>(g);
        combine_kernel<<<(B_ * cnt * 128 + 255) / 256, 256>>>(p_lvl, p_feiou,
                                                              p_h, p_c, p_hs, start, cnt);
    }
    // 5) output pooling
    dot_kernel<<<(B_ * NN * 32 + 255) / 256, 256>>>(p_h, p_ef, p_lg);
    final_kernel<<<B_, F_>>>(p_lg, p_h, out);
}